// round 16
// baseline (speedup 1.0000x reference)
#include <cuda_runtime.h>
#include <cuda_bf16.h>
#include <cstdint>

#define NMAX 20000
#define EMAX 320000
#define ETOT_MAX (EMAX + NMAX)
#define HID 256
#define HEADS 8

// ---------------- scratch (device globals; no allocation) ----------------
__device__ float g_xmlp[NMAX * HID];
__device__ float g_g[NMAX * HID];
__device__ float g_xlr[NMAX * 2 * HID];     // [N][512]: xl | xr
__device__ float g_t3[NMAX * 64];
__device__ int   g_cnt[NMAX];
__device__ int   g_cursor[NMAX];
__device__ int   g_rowptr[NMAX + 1];
__device__ int   g_csr_src[ETOT_MAX];
// bf16 hi/lo activation buffers
__device__ __nv_bfloat16 g_xhi[NMAX * 128],  g_xlo[NMAX * 128];
__device__ __nv_bfloat16 g_h1hi[NMAX * HID], g_h1lo[NMAX * HID];
__device__ __nv_bfloat16 g_h2hi[NMAX * HID], g_h2lo[NMAX * HID];
__device__ __nv_bfloat16 g_xmhi[NMAX * HID], g_xmlo[NMAX * HID];
__device__ __nv_bfloat16 g_ghi[NMAX * HID],  g_glo[NMAX * HID];
__device__ __nv_bfloat16 g_t1hi[NMAX * HID], g_t1lo[NMAX * HID];
__device__ __nv_bfloat16 g_t2hi[NMAX * 128], g_t2lo[NMAX * 128];
// transposed + bf16-split weights: total 860160 elems
#define WTOT 860160
__device__ __nv_bfloat16 g_wthi[WTOT];
__device__ __nv_bfloat16 g_wtlo[WTOT];

// ---------------- helpers --------------------------------------------------
__device__ __forceinline__ uint32_t smem_u32(const void* p) {
    return (uint32_t)__cvta_generic_to_shared(p);
}
__device__ __forceinline__ void ldsm4(uint32_t r[4], uint32_t addr) {
    asm volatile("ldmatrix.sync.aligned.m8n8.x4.shared.b16 {%0,%1,%2,%3}, [%4];"
        : "=r"(r[0]), "=r"(r[1]), "=r"(r[2]), "=r"(r[3]) : "r"(addr));
}
__device__ __forceinline__ void mma16816(float c[4], const uint32_t a[4], const uint32_t b[2]) {
    asm volatile("mma.sync.aligned.m16n8k16.row.col.f32.bf16.bf16.f32 "
        "{%0,%1,%2,%3}, {%4,%5,%6,%7}, {%8,%9}, {%0,%1,%2,%3};"
        : "+f"(c[0]), "+f"(c[1]), "+f"(c[2]), "+f"(c[3])
        : "r"(a[0]), "r"(a[1]), "r"(a[2]), "r"(a[3]), "r"(b[0]), "r"(b[1]));
}
__device__ __forceinline__ void cp16(uint32_t dst, const void* src, bool pred) {
    int sz = pred ? 16 : 0;
    asm volatile("cp.async.cg.shared.global [%0], [%1], 16, %2;"
                 :: "r"(dst), "l"(src), "r"(sz));
}
__device__ __forceinline__ void cp_commit() {
    asm volatile("cp.async.commit_group;");
}
__device__ __forceinline__ void cp_wait1() {
    asm volatile("cp.async.wait_group 1;");
}
__device__ __forceinline__ void cp_wait0() {
    asm volatile("cp.async.wait_group 0;");
}

// =========================================================================
// bf16 3-split tensor-core GEMM. BM=64, BN=128, 256 threads (8 warps 2m x 4n).
// NEW: K-chunk = 16, 3 stages (18.4KB each) -> 55.3KB/CTA -> 3 CTAs/SM with a
// full chunk of cp.async prefetch slack (wait_group 1). One barrier per chunk.
// C = act(bn(A @ W + bias)); A given as bf16 hi/lo (optionally split A|A2 at
// column Ks, Ks mult of 16). Outputs: Cf (fp32) and/or Chi/Clo (bf16 split).
// mode: 0 bias, 1 bias+bn+lrelu0.1, 2 bias+lrelu0.1
// =========================================================================
#define ASTR 24                       // smem row stride in bf16 (16 + 8 pad)
#define STG_ROWS 384                  // 64(Ahi)+64(Alo)+128(Bhi)+128(Blo)
#define NSTAGE 3
#define GEMM_SMEM (NSTAGE * STG_ROWS * ASTR * 2)   // 55296 B

__global__ __launch_bounds__(256, 3)
void gemm_mma_kernel(const __nv_bfloat16* __restrict__ Ahi,
                     const __nv_bfloat16* __restrict__ Alo,
                     const __nv_bfloat16* __restrict__ A2hi,
                     const __nv_bfloat16* __restrict__ A2lo, int Ks,
                     const __nv_bfloat16* __restrict__ Whi,
                     const __nv_bfloat16* __restrict__ Wlo,
                     const float* __restrict__ bias,
                     const float* __restrict__ bias2, int bhalf,
                     const float* __restrict__ bn_g,
                     const float* __restrict__ bn_b,
                     float* __restrict__ Cf,
                     __nv_bfloat16* __restrict__ Chi,
                     __nv_bfloat16* __restrict__ Clo,
                     int M, int Nc, int K, int mode)
{
    extern __shared__ __nv_bfloat16 smem[];

    const int tid = threadIdx.x;
    const int wid = tid >> 5;
    const int lane = tid & 31;
    const int warp_m = wid >> 2;
    const int warp_n = wid & 3;
    const int m0 = blockIdx.y * 64;
    const int n0 = blockIdx.x * 128;

    float acc[2][4][4] = {};
    const int NCH = K >> 4;           // 16-float K chunks

    // loader coords: A piece (1/thread): threads 0-127 -> A-hi, 128-255 -> A-lo
    const int a_row  = (tid & 127) >> 1;        // 0..63
    const int a_col  = (tid & 1) * 8;           // 0 or 8
    const bool a_lo  = tid >= 128;
    // B pieces (2/thread): row = tid>>1 (0..127), col = (tid&1)*8
    const int b_row  = tid >> 1;
    const int b_col  = (tid & 1) * 8;

    auto issue = [&](int c) {
        uint32_t sb = smem_u32(smem + (c % NSTAGE) * (STG_ROWS * ASTR));
        int k0 = c * 16;
        // A (hi or lo depending on thread half)
        {
            int grow = m0 + a_row;
            bool ap = grow < M;
            int gr = ap ? grow : (M - 1);
            const __nv_bfloat16* src;
            if (k0 < Ks)
                src = (a_lo ? Alo : Ahi) + (size_t)gr * Ks + k0 + a_col;
            else
                src = (a_lo ? A2lo : A2hi) + (size_t)gr * (K - Ks) + (k0 - Ks) + a_col;
            int srow = a_lo ? (64 + a_row) : a_row;
            cp16(sb + (uint32_t)(srow * ASTR + a_col) * 2, src, ap);
        }
        // B hi + lo
        {
            int gn = n0 + b_row;
            bool bp = gn < Nc;
            int gc = bp ? gn : (Nc - 1);
            cp16(sb + (uint32_t)((128 + b_row) * ASTR + b_col) * 2,
                 Whi + (size_t)gc * K + k0 + b_col, bp);
            cp16(sb + (uint32_t)((256 + b_row) * ASTR + b_col) * 2,
                 Wlo + (size_t)gc * K + k0 + b_col, bp);
        }
        cp_commit();
    };

    issue(0);
    if (NCH > 1) issue(1);

    for (int c = 0; c < NCH; c++) {
        if (c + 1 < NCH) cp_wait1(); else cp_wait0();
        __syncthreads();
        if (c + 2 < NCH) issue(c + 2);

        __nv_bfloat16* base = smem + (c % NSTAGE) * (STG_ROWS * ASTR);
        __nv_bfloat16* sAhi = base;
        __nv_bfloat16* sAlo = base + 64 * ASTR;
        __nv_bfloat16* sBhi = base + 128 * ASTR;
        __nv_bfloat16* sBlo = base + 256 * ASTR;

        uint32_t ahi[2][4], alo[2][4];
        #pragma unroll
        for (int mi = 0; mi < 2; mi++) {
            int row = warp_m * 32 + mi * 16 + (lane & 15);
            int col = (lane >> 4) << 3;
            ldsm4(ahi[mi], smem_u32(&sAhi[row * ASTR + col]));
            ldsm4(alo[mi], smem_u32(&sAlo[row * ASTR + col]));
        }
        uint32_t bhi[4][2], blo[4][2];
        #pragma unroll
        for (int pj = 0; pj < 2; pj++) {
            int row = warp_n * 32 + pj * 16 + ((lane & 16) >> 1) + (lane & 7);
            int col = lane & 8;
            uint32_t r4[4];
            ldsm4(r4, smem_u32(&sBhi[row * ASTR + col]));
            bhi[pj * 2][0] = r4[0]; bhi[pj * 2][1] = r4[1];
            bhi[pj * 2 + 1][0] = r4[2]; bhi[pj * 2 + 1][1] = r4[3];
            ldsm4(r4, smem_u32(&sBlo[row * ASTR + col]));
            blo[pj * 2][0] = r4[0]; blo[pj * 2][1] = r4[1];
            blo[pj * 2 + 1][0] = r4[2]; blo[pj * 2 + 1][1] = r4[3];
        }
        #pragma unroll
        for (int mi = 0; mi < 2; mi++)
            #pragma unroll
            for (int nj = 0; nj < 4; nj++)
                mma16816(acc[mi][nj], ahi[mi], bhi[nj]);
        #pragma unroll
        for (int mi = 0; mi < 2; mi++)
            #pragma unroll
            for (int nj = 0; nj < 4; nj++)
                mma16816(acc[mi][nj], alo[mi], bhi[nj]);
        #pragma unroll
        for (int mi = 0; mi < 2; mi++)
            #pragma unroll
            for (int nj = 0; nj < 4; nj++)
                mma16816(acc[mi][nj], ahi[mi], blo[nj]);
        // no trailing sync: next iteration's __syncthreads orders compute(c)
        // before issue(c+3), which is the first writer of this buffer.
    }

    // epilogue
    const float inv_bn = rsqrtf(1.f + 1e-5f);
    float sc[4][2], sh[4][2];
    #pragma unroll
    for (int nj = 0; nj < 4; nj++) {
        int cb = n0 + warp_n * 32 + nj * 8 + 2 * (lane & 3);
        #pragma unroll
        for (int h = 0; h < 2; h++) {
            int col = cb + h;
            int cg = (col < Nc) ? col : 0;
            float b = (cg < bhalf) ? bias[cg] : bias2[cg - bhalf];
            if (mode == 1) {
                float s = bn_g[cg] * inv_bn;
                sc[nj][h] = s; sh[nj][h] = b * s + bn_b[cg];
            } else {
                sc[nj][h] = 1.f; sh[nj][h] = b;
            }
        }
    }
    const bool act = (mode != 0);
    #pragma unroll
    for (int mi = 0; mi < 2; mi++) {
        int rA = m0 + warp_m * 32 + mi * 16 + (lane >> 2);
        int rB = rA + 8;
        #pragma unroll
        for (int nj = 0; nj < 4; nj++) {
            int cb = n0 + warp_n * 32 + nj * 8 + 2 * (lane & 3);
            if (cb >= Nc) continue;
            float2 v0, v1;
            v0.x = acc[mi][nj][0] * sc[nj][0] + sh[nj][0];
            v0.y = acc[mi][nj][1] * sc[nj][1] + sh[nj][1];
            v1.x = acc[mi][nj][2] * sc[nj][0] + sh[nj][0];
            v1.y = acc[mi][nj][3] * sc[nj][1] + sh[nj][1];
            if (act) {
                v0.x = v0.x > 0.f ? v0.x : 0.1f * v0.x;
                v0.y = v0.y > 0.f ? v0.y : 0.1f * v0.y;
                v1.x = v1.x > 0.f ? v1.x : 0.1f * v1.x;
                v1.y = v1.y > 0.f ? v1.y : 0.1f * v1.y;
            }
            if (Cf) {
                if (rA < M) *reinterpret_cast<float2*>(&Cf[(size_t)rA * Nc + cb]) = v0;
                if (rB < M) *reinterpret_cast<float2*>(&Cf[(size_t)rB * Nc + cb]) = v1;
            }
            if (Chi) {
                __nv_bfloat16 h0 = __float2bfloat16_rn(v0.x);
                __nv_bfloat16 h1 = __float2bfloat16_rn(v0.y);
                __nv_bfloat16 h2 = __float2bfloat16_rn(v1.x);
                __nv_bfloat16 h3 = __float2bfloat16_rn(v1.y);
                __nv_bfloat162 phA = __halves2bfloat162(h0, h1);
                __nv_bfloat162 phB = __halves2bfloat162(h2, h3);
                __nv_bfloat162 plA = __halves2bfloat162(
                    __float2bfloat16_rn(v0.x - __bfloat162float(h0)),
                    __float2bfloat16_rn(v0.y - __bfloat162float(h1)));
                __nv_bfloat162 plB = __halves2bfloat162(
                    __float2bfloat16_rn(v1.x - __bfloat162float(h2)),
                    __float2bfloat16_rn(v1.y - __bfloat162float(h3)));
                if (rA < M) {
                    *reinterpret_cast<__nv_bfloat162*>(&Chi[(size_t)rA * Nc + cb]) = phA;
                    *reinterpret_cast<__nv_bfloat162*>(&Clo[(size_t)rA * Nc + cb]) = plA;
                }
                if (rB < M) {
                    *reinterpret_cast<__nv_bfloat162*>(&Chi[(size_t)rB * Nc + cb]) = phB;
                    *reinterpret_cast<__nv_bfloat162*>(&Clo[(size_t)rB * Nc + cb]) = plB;
                }
            }
        }
    }
}

// ---------------- activation split prep (for x input) ---------------------
__global__ void aprep_kernel(const float* __restrict__ A,
                             __nv_bfloat16* __restrict__ hi,
                             __nv_bfloat16* __restrict__ lo, int n)
{
    int i = blockIdx.x * blockDim.x + threadIdx.x;
    if (i >= n) return;
    float v = A[i];
    __nv_bfloat16 h = __float2bfloat16_rn(v);
    hi[i] = h;
    lo[i] = __float2bfloat16_rn(v - __bfloat162float(h));
}

// ---------------- fused weight prep (all 14 matrices, one launch) ---------
struct WPEntry { const float* W; int K; int lgNc; int off; int start; };
struct WPArgs  { WPEntry e[14]; int total; };

__global__ void wprep_all_kernel(WPArgs args,
                                 __nv_bfloat16* __restrict__ Wt_hi,
                                 __nv_bfloat16* __restrict__ Wt_lo)
{
    int gid = blockIdx.x * blockDim.x + threadIdx.x;
    if (gid >= args.total) return;
    int r = 0;
    #pragma unroll
    for (int i = 1; i < 14; i++)
        if (gid >= args.e[i].start) r = i;
    const WPEntry& en = args.e[r];
    int e = gid - en.start;
    int k = e >> en.lgNc;
    int n = e & ((1 << en.lgNc) - 1);
    float v = en.W[e];
    __nv_bfloat16 hi = __float2bfloat16_rn(v);
    size_t dst = (size_t)en.off + (size_t)n * en.K + k;
    Wt_hi[dst] = hi;
    Wt_lo[dst] = __float2bfloat16_rn(v - __bfloat162float(hi));
}

// ---------------- CSR build ------------------------------------------------
__global__ void hist_kernel(const int* __restrict__ ei, int* __restrict__ cnt,
                            int E, int N)
{
    int i = blockIdx.x * blockDim.x + threadIdx.x;
    int Et = E + N;
    if (i >= Et) return;
    int d = (i < E) ? ei[E + i] : (i - E);
    atomicAdd(&cnt[d], 1);
}

__global__ __launch_bounds__(1024)
void scan_kernel(const int* __restrict__ cnt, int* __restrict__ rowptr,
                 int* __restrict__ cursor, int N)
{
    __shared__ int part[1024];
    const int t = threadIdx.x;
    const int CH = (N + 1023) / 1024;
    int base = t * CH;
    int s = 0;
    for (int i = 0; i < CH; i++)
        if (base + i < N) s += cnt[base + i];
    part[t] = s;
    __syncthreads();
    for (int d = 1; d < 1024; d <<= 1) {
        int v = (t >= d) ? part[t - d] : 0;
        __syncthreads();
        part[t] += v;
        __syncthreads();
    }
    int run = part[t] - s;
    for (int i = 0; i < CH; i++) {
        int idx = base + i;
        if (idx < N) {
            rowptr[idx] = run;
            cursor[idx] = run;
            run += cnt[idx];
        }
    }
    if (t == 0) rowptr[N] = part[1023];
}

__global__ void fill_kernel(const int* __restrict__ ei, int* __restrict__ cursor,
                            int* __restrict__ csr_src, int E, int N)
{
    int i = blockIdx.x * blockDim.x + threadIdx.x;
    int Et = E + N;
    if (i >= Et) return;
    int s, d;
    if (i < E) { s = ei[i]; d = ei[E + i]; }
    else       { s = d = i - E; }
    int p = atomicAdd(&cursor[d], 1);
    csr_src[p] = s;
}

// =========================================================================
// Fused GAT layer (champion version): warp per dst node, online softmax,
// depth-1 prefetch; bias + LayerNorm + LeakyReLU(0.1) + residual; writes g
// (fp32) and its bf16 hi/lo split.
// xlr layout [N][512]: xl cols 0-255, xr cols 256-511.
// =========================================================================
__global__ __launch_bounds__(256)
void gat_fused_kernel(const float* __restrict__ xlr,
                      const int* __restrict__ csr_src,
                      const int* __restrict__ rowptr,
                      const float* __restrict__ att,
                      const float* __restrict__ gbias,
                      const float* __restrict__ lng,
                      const float* __restrict__ lnb,
                      const float* __restrict__ gres,
                      float* __restrict__ g,
                      __nv_bfloat16* __restrict__ ghi,
                      __nv_bfloat16* __restrict__ glo, int N)
{
    int warp = (blockIdx.x * blockDim.x + threadIdx.x) >> 5;
    int lane = threadIdx.x & 31;
    if (warp >= N) return;
    const int cb = lane * 8;

    float4 xr0 = *reinterpret_cast<const float4*>(xlr + (size_t)warp * 512 + 256 + cb);
    float4 xr1 = *reinterpret_cast<const float4*>(xlr + (size_t)warp * 512 + 256 + cb + 4);
    float4 at0 = *reinterpret_cast<const float4*>(att + cb);
    float4 at1 = *reinterpret_cast<const float4*>(att + cb + 4);

    int beg = rowptr[warp], end = rowptr[warp + 1];

    float m = -1e30f, s = 0.f;
    float acc[8] = {};

    float4 a0, a1;
    {
        int sidx = csr_src[beg];
        a0 = *reinterpret_cast<const float4*>(xlr + (size_t)sidx * 512 + cb);
        a1 = *reinterpret_cast<const float4*>(xlr + (size_t)sidx * 512 + cb + 4);
    }

    for (int j = beg; j < end; j++) {
        float4 c0 = a0, c1 = a1;
        if (j + 1 < end) {
            int sidx = csr_src[j + 1];
            a0 = *reinterpret_cast<const float4*>(xlr + (size_t)sidx * 512 + cb);
            a1 = *reinterpret_cast<const float4*>(xlr + (size_t)sidx * 512 + cb + 4);
        }
        float t, p = 0.f;
        t = c0.x + xr0.x; t = t > 0.f ? t : 0.2f * t; p += t * at0.x;
        t = c0.y + xr0.y; t = t > 0.f ? t : 0.2f * t; p += t * at0.y;
        t = c0.z + xr0.z; t = t > 0.f ? t : 0.2f * t; p += t * at0.z;
        t = c0.w + xr0.w; t = t > 0.f ? t : 0.2f * t; p += t * at0.w;
        t = c1.x + xr1.x; t = t > 0.f ? t : 0.2f * t; p += t * at1.x;
        t = c1.y + xr1.y; t = t > 0.f ? t : 0.2f * t; p += t * at1.y;
        t = c1.z + xr1.z; t = t > 0.f ? t : 0.2f * t; p += t * at1.z;
        t = c1.w + xr1.w; t = t > 0.f ? t : 0.2f * t; p += t * at1.w;
        p += __shfl_xor_sync(0xffffffffu, p, 1);
        p += __shfl_xor_sync(0xffffffffu, p, 2);
        float mn = fmaxf(m, p);
        float cf = __expf(m - mn);
        float w  = __expf(p - mn);
        m = mn;
        s = s * cf + w;
        acc[0] = acc[0] * cf + w * c0.x;
        acc[1] = acc[1] * cf + w * c0.y;
        acc[2] = acc[2] * cf + w * c0.z;
        acc[3] = acc[3] * cf + w * c0.w;
        acc[4] = acc[4] * cf + w * c1.x;
        acc[5] = acc[5] * cf + w * c1.y;
        acc[6] = acc[6] * cf + w * c1.z;
        acc[7] = acc[7] * cf + w * c1.w;
    }

    float inv_s = 1.f / (s + 1e-16f);
    float out[8];
    {
        float4 b0 = *reinterpret_cast<const float4*>(gbias + cb);
        float4 b1 = *reinterpret_cast<const float4*>(gbias + cb + 4);
        out[0] = acc[0] * inv_s + b0.x;
        out[1] = acc[1] * inv_s + b0.y;
        out[2] = acc[2] * inv_s + b0.z;
        out[3] = acc[3] * inv_s + b0.w;
        out[4] = acc[4] * inv_s + b1.x;
        out[5] = acc[5] * inv_s + b1.y;
        out[6] = acc[6] * inv_s + b1.z;
        out[7] = acc[7] * inv_s + b1.w;
    }
    float sum = 0.f;
    #pragma unroll
    for (int i = 0; i < 8; i++) sum += out[i];
    #pragma unroll
    for (int o = 16; o; o >>= 1) sum += __shfl_xor_sync(0xffffffffu, sum, o);
    float mu = sum * (1.f / 256.f);
    float var = 0.f;
    #pragma unroll
    for (int i = 0; i < 8; i++) { float dd = out[i] - mu; var += dd * dd; }
    #pragma unroll
    for (int o = 16; o; o >>= 1) var += __shfl_xor_sync(0xffffffffu, var, o);
    var *= (1.f / 256.f);
    float inv = rsqrtf(var + 1e-5f);

    float4 lg0 = *reinterpret_cast<const float4*>(lng + cb);
    float4 lg1 = *reinterpret_cast<const float4*>(lng + cb + 4);
    float4 lb0 = *reinterpret_cast<const float4*>(lnb + cb);
    float4 lb1 = *reinterpret_cast<const float4*>(lnb + cb + 4);
    const float* rrow = gres + (size_t)warp * HID + cb;
    float4 g0 = *reinterpret_cast<const float4*>(rrow);
    float4 g1 = *reinterpret_cast<const float4*>(rrow + 4);

    float lgv[8] = {lg0.x, lg0.y, lg0.z, lg0.w, lg1.x, lg1.y, lg1.z, lg1.w};
    float lbv[8] = {lb0.x, lb0.y, lb0.z, lb0.w, lb1.x, lb1.y, lb1.z, lb1.w};
    float gv[8]  = {g0.x, g0.y, g0.z, g0.w, g1.x, g1.y, g1.z, g1.w};
    #pragma unroll
    for (int i = 0; i < 8; i++) {
        float o_ = (out[i] - mu) * inv * lgv[i] + lbv[i];
        o_ = o_ > 0.f ? o_ : 0.1f * o_;
        gv[i] += o_;
    }
    float* grow = g + (size_t)warp * HID + cb;
    *reinterpret_cast<float4*>(grow)     = make_float4(gv[0], gv[1], gv[2], gv[3]);
    *reinterpret_cast<float4*>(grow + 4) = make_float4(gv[4], gv[5], gv[6], gv[7]);

    union { __nv_bfloat162 b[4]; uint4 u; } ph, pl;
    #pragma unroll
    for (int i = 0; i < 4; i++) {
        __nv_bfloat16 h0 = __float2bfloat16_rn(gv[2 * i]);
        __nv_bfloat16 h1 = __float2bfloat16_rn(gv[2 * i + 1]);
        ph.b[i] = __halves2bfloat162(h0, h1);
        pl.b[i] = __halves2bfloat162(
            __float2bfloat16_rn(gv[2 * i]     - __bfloat162float(h0)),
            __float2bfloat16_rn(gv[2 * i + 1] - __bfloat162float(h1)));
    }
    *reinterpret_cast<uint4*>(ghi + (size_t)warp * HID + cb) = ph.u;
    *reinterpret_cast<uint4*>(glo + (size_t)warp * HID + cb) = pl.u;
}

// ---------------- final head: out = t3 @ w4 + b4 -------------------------
__global__ void head_final_kernel(const float* __restrict__ t3,
                                  const float* __restrict__ w4,
                                  const float* __restrict__ b4,
                                  float* __restrict__ out, int N)
{
    int warp = (blockIdx.x * blockDim.x + threadIdx.x) >> 5;
    int lane = threadIdx.x & 31;
    if (warp >= N) return;
    const float* r = t3 + (size_t)warp * 64;
    float acc = r[lane] * w4[lane] + r[lane + 32] * w4[lane + 32];
    #pragma unroll
    for (int o = 16; o; o >>= 1) acc += __shfl_xor_sync(0xffffffffu, acc, o);
    if (lane == 0) out[warp] = acc + b4[0];
}

// =========================================================================
extern "C" void kernel_launch(void* const* d_in, const int* in_sizes, int n_in,
                              void* d_out, int out_size)
{
    const float* x       = (const float*)d_in[0];
    const int*   ei      = (const int*)  d_in[1];
    const float* mlp_w1  = (const float*)d_in[2];
    const float* mlp_b1  = (const float*)d_in[3];
    const float* bn1_g   = (const float*)d_in[4];
    const float* bn1_b   = (const float*)d_in[5];
    const float* mlp_w2  = (const float*)d_in[6];
    const float* mlp_b2  = (const float*)d_in[7];
    const float* bn2_g   = (const float*)d_in[8];
    const float* bn2_b   = (const float*)d_in[9];
    const float* mlp_w3  = (const float*)d_in[10];
    const float* mlp_b3  = (const float*)d_in[11];
    const float* gat_wl  = (const float*)d_in[12];
    const float* gat_bl  = (const float*)d_in[13];
    const float* gat_wr  = (const float*)d_in[14];
    const float* gat_br  = (const float*)d_in[15];
    const float* gat_att = (const float*)d_in[16];
    const float* gat_bias= (const float*)d_in[17];
    const float* ln_g    = (const float*)d_in[18];
    const float* ln_b    = (const float*)d_in[19];
    const float* head_w1 = (const float*)d_in[20];
    const float* head_b1 = (const float*)d_in[21];
    const float* hbn1_g  = (const float*)d_in[22];
    const float* hbn1_b  = (const float*)d_in[23];
    const float* head_w2 = (const float*)d_in[24];
    const float* head_b2 = (const float*)d_in[25];
    const float* hbn2_g  = (const float*)d_in[26];
    const float* hbn2_b  = (const float*)d_in[27];
    const float* head_w3 = (const float*)d_in[28];
    const float* head_b3 = (const float*)d_in[29];
    const float* head_w4 = (const float*)d_in[30];
    const float* head_b4 = (const float*)d_in[31];

    int N = in_sizes[0] / 128;
    int E = in_sizes[1] / 2;
    if (N > NMAX) N = NMAX;
    if (E > EMAX) E = EMAX;
    int Et = E + N;

    float *xmlp, *g, *xlr, *t3;
    int *cnt, *cursor, *rowptr, *csr_src;
    __nv_bfloat16 *whi, *wlo, *xhi, *xlo, *h1hi, *h1lo, *h2hi, *h2lo;
    __nv_bfloat16 *xmhi, *xmlo, *ghi, *glo, *t1hi, *t1lo, *t2hi, *t2lo;
    cudaGetSymbolAddress((void**)&xmlp,    g_xmlp);
    cudaGetSymbolAddress((void**)&g,       g_g);
    cudaGetSymbolAddress((void**)&xlr,     g_xlr);
    cudaGetSymbolAddress((void**)&t3,      g_t3);
    cudaGetSymbolAddress((void**)&cnt,     g_cnt);
    cudaGetSymbolAddress((void**)&cursor,  g_cursor);
    cudaGetSymbolAddress((void**)&rowptr,  g_rowptr);
    cudaGetSymbolAddress((void**)&csr_src, g_csr_src);
    cudaGetSymbolAddress((void**)&whi,     g_wthi);
    cudaGetSymbolAddress((void**)&wlo,     g_wtlo);
    cudaGetSymbolAddress((void**)&xhi,     g_xhi);
    cudaGetSymbolAddress((void**)&xlo,     g_xlo);
    cudaGetSymbolAddress((void**)&h1hi,    g_h1hi);
    cudaGetSymbolAddress((void**)&h1lo,    g_h1lo);
    cudaGetSymbolAddress((void**)&h2hi,    g_h2hi);
    cudaGetSymbolAddress((void**)&h2lo,    g_h2lo);
    cudaGetSymbolAddress((void**)&xmhi,    g_xmhi);
    cudaGetSymbolAddress((void**)&xmlo,    g_xmlo);
    cudaGetSymbolAddress((void**)&ghi,     g_ghi);
    cudaGetSymbolAddress((void**)&glo,     g_glo);
    cudaGetSymbolAddress((void**)&t1hi,    g_t1hi);
    cudaGetSymbolAddress((void**)&t1lo,    g_t1lo);
    cudaGetSymbolAddress((void**)&t2hi,    g_t2hi);
    cudaGetSymbolAddress((void**)&t2lo,    g_t2lo);

    cudaFuncSetAttribute(gemm_mma_kernel,
                         cudaFuncAttributeMaxDynamicSharedMemorySize, GEMM_SMEM);

    dim3 blk(256);
    const int OFF_M1 = 0;
    const int OFF_M2 = 32768;
    const int OFF_M3 = 98304;
    const int OFF_GAT = 163840;
    const int OFF_H1 = 688128;
    const int OFF_H2 = 819200;
    const int OFF_H3 = 851968;

    WPArgs wa;
    int cur = 0, idx = 0;
    auto addw = [&](const float* W, int K, int lg, int off) {
        wa.e[idx].W = W; wa.e[idx].K = K; wa.e[idx].lgNc = lg;
        wa.e[idx].off = off; wa.e[idx].start = cur;
        cur += K << lg; idx++;
    };
    addw(mlp_w1, 128, 8, OFF_M1);
    addw(mlp_w2, 256, 8, OFF_M2);
    addw(mlp_w3, 256, 8, OFF_M3);
    for (int l = 0; l < 4; l++) {
        addw(gat_wl + (size_t)l * 65536, 256, 8, OFF_GAT + l * 131072);
        addw(gat_wr + (size_t)l * 65536, 256, 8, OFF_GAT + l * 131072 + 65536);
    }
    addw(head_w1, 512, 8, OFF_H1);
    addw(head_w2, 256, 7, OFF_H2);
    addw(head_w3, 128, 6, OFF_H3);
    wa.total = cur;
    wprep_all_kernel<<<(cur + 255) / 256, blk>>>(wa, whi, wlo);
    aprep_kernel<<<(N * 128 + 255) / 256, blk>>>(x, xhi, xlo, N * 128);

    const int BIG = 1 << 30;
    auto mm = [&](const __nv_bfloat16* Ahi, const __nv_bfloat16* Alo,
                  const __nv_bfloat16* A2hi, const __nv_bfloat16* A2lo, int Ks,
                  int off, const float* bias, const float* bias2, int bhalf,
                  const float* bg, const float* bb,
                  float* Cf, __nv_bfloat16* Chi, __nv_bfloat16* Clo,
                  int Nc, int K, int mode) {
        dim3 grid((unsigned)((Nc + 127) / 128), (unsigned)((N + 63) / 64));
        gemm_mma_kernel<<<grid, blk, GEMM_SMEM>>>(Ahi, Alo,
            A2hi ? A2hi : Ahi, A2lo ? A2lo : Alo, Ks,
            whi + off, wlo + off, bias, bias2 ? bias2 : bias, bhalf,
            bg, bb, Cf, Chi, Clo, N, Nc, K, mode);
    };

    // Feature MLP
    mm(xhi, xlo, nullptr, nullptr, 128, OFF_M1, mlp_b1, nullptr, BIG,
       bn1_g, bn1_b, nullptr, h1hi, h1lo, 256, 128, 1);
    mm(h1hi, h1lo, nullptr, nullptr, 256, OFF_M2, mlp_b2, nullptr, BIG,
       bn2_g, bn2_b, nullptr, h2hi, h2lo, 256, 256, 1);
    mm(h2hi, h2lo, nullptr, nullptr, 256, OFF_M3, mlp_b3, nullptr, BIG,
       nullptr, nullptr, xmlp, xmhi, xmlo, 256, 256, 0);

    // layer 0 merged xl|xr GEMM
    mm(xmhi, xmlo, nullptr, nullptr, 256, OFF_GAT, gat_bl, gat_br, 256,
       nullptr, nullptr, xlr, nullptr, nullptr, 512, 256, 0);

    // ---- CSR build --------------------------------------------------------
    cudaMemsetAsync(cnt, 0, (size_t)N * sizeof(int));
    hist_kernel<<<(Et + 255) / 256, blk>>>(ei, cnt, E, N);
    scan_kernel<<<1, 1024>>>(cnt, rowptr, cursor, N);
    fill_kernel<<<(Et + 255) / 256, blk>>>(ei, cursor, csr_src, E, N);

    const int gat_grid = (N * 32 + 255) / 256;
    for (int l = 0; l < 4; l++) {
        const float* at  = gat_att + (size_t)l * 256;
        const float* gb  = gat_bias+ (size_t)l * 256;
        const float* lg  = ln_g    + (size_t)l * 256;
        const float* lb  = ln_b    + (size_t)l * 256;

        if (l > 0) {
            mm(ghi, glo, nullptr, nullptr, 256, OFF_GAT + l * 131072,
               gat_bl + (size_t)l * 256, gat_br + (size_t)l * 256, 256,
               nullptr, nullptr, xlr, nullptr, nullptr, 512, 256, 0);
        }
        gat_fused_kernel<<<gat_grid, blk>>>(xlr, csr_src, rowptr, at, gb, lg, lb,
                                            (l == 0) ? xmlp : g, g, ghi, glo, N);
    }

    // head (concat fused via A|A2 split)
    mm(xmhi, xmlo, ghi, glo, 256, OFF_H1, head_b1, nullptr, BIG,
       hbn1_g, hbn1_b, nullptr, t1hi, t1lo, 256, 512, 1);
    mm(t1hi, t1lo, nullptr, nullptr, 256, OFF_H2, head_b2, nullptr, BIG,
       hbn2_g, hbn2_b, nullptr, t2hi, t2lo, 128, 256, 1);
    mm(t2hi, t2lo, nullptr, nullptr, 128, OFF_H3, head_b3, nullptr, BIG,
       nullptr, nullptr, t3, nullptr, nullptr, 64, 128, 2);
    head_final_kernel<<<(N * 32 + 255) / 256, blk>>>(t3, head_w4, head_b4, (float*)d_out, N);
}

// round 17
// speedup vs baseline: 1.1155x; 1.1155x over previous
#include <cuda_runtime.h>
#include <cuda_bf16.h>
#include <cstdint>

#define NMAX 20000
#define EMAX 320000
#define ETOT_MAX (EMAX + NMAX)
#define HID 256
#define HEADS 8

// ---------------- scratch (device globals; no allocation) ----------------
__device__ float g_xmlp[NMAX * HID];
__device__ float g_g[NMAX * HID];
__device__ float g_xlr[NMAX * 2 * HID];     // [N][512]: xl | xr
__device__ int   g_cnt[NMAX];
__device__ int   g_cursor[NMAX];
__device__ int   g_rowptr[NMAX + 1];
__device__ int   g_csr_src[ETOT_MAX];
// bf16 hi/lo activation buffers
__device__ __nv_bfloat16 g_xhi[NMAX * 128],  g_xlo[NMAX * 128];
__device__ __nv_bfloat16 g_h1hi[NMAX * HID], g_h1lo[NMAX * HID];
__device__ __nv_bfloat16 g_h2hi[NMAX * HID], g_h2lo[NMAX * HID];
__device__ __nv_bfloat16 g_xmhi[NMAX * HID], g_xmlo[NMAX * HID];
__device__ __nv_bfloat16 g_ghi[NMAX * HID],  g_glo[NMAX * HID];
__device__ __nv_bfloat16 g_t1hi[NMAX * HID], g_t1lo[NMAX * HID];
__device__ __nv_bfloat16 g_t2hi[NMAX * 128], g_t2lo[NMAX * 128];
// transposed + bf16-split weights: total 860160 elems
#define WTOT 860160
__device__ __nv_bfloat16 g_wthi[WTOT];
__device__ __nv_bfloat16 g_wtlo[WTOT];

// ---------------- helpers --------------------------------------------------
__device__ __forceinline__ uint32_t smem_u32(const void* p) {
    return (uint32_t)__cvta_generic_to_shared(p);
}
__device__ __forceinline__ void ldsm4(uint32_t r[4], uint32_t addr) {
    asm volatile("ldmatrix.sync.aligned.m8n8.x4.shared.b16 {%0,%1,%2,%3}, [%4];"
        : "=r"(r[0]), "=r"(r[1]), "=r"(r[2]), "=r"(r[3]) : "r"(addr));
}
__device__ __forceinline__ void mma16816(float c[4], const uint32_t a[4], const uint32_t b[2]) {
    asm volatile("mma.sync.aligned.m16n8k16.row.col.f32.bf16.bf16.f32 "
        "{%0,%1,%2,%3}, {%4,%5,%6,%7}, {%8,%9}, {%0,%1,%2,%3};"
        : "+f"(c[0]), "+f"(c[1]), "+f"(c[2]), "+f"(c[3])
        : "r"(a[0]), "r"(a[1]), "r"(a[2]), "r"(a[3]), "r"(b[0]), "r"(b[1]));
}
__device__ __forceinline__ void cp16(uint32_t dst, const void* src, bool pred) {
    int sz = pred ? 16 : 0;
    asm volatile("cp.async.cg.shared.global [%0], [%1], 16, %2;"
                 :: "r"(dst), "l"(src), "r"(sz));
}
__device__ __forceinline__ void cp_commit() {
    asm volatile("cp.async.commit_group;");
}
__device__ __forceinline__ void cp_wait0() {
    asm volatile("cp.async.wait_group 0;");
}

// =========================================================================
// bf16 3-split tensor-core GEMM (champion mainloop, frozen).
// 2 stages -> 61440B smem -> 3 CTAs/SM. BM=64, BN=128, 256 threads.
// C = act(bn(A @ W + bias)); A given as bf16 hi/lo (optionally split A|A2
// at column Ks). Outputs: Cf (fp32) and/or Chi/Clo (bf16 split).
// mode: 0 bias, 1 bias+bn+lrelu0.1, 2 bias+lrelu0.1,
//       3 bias+lrelu0.1 then fused dot with w4 -> atomicAdd outp[row]
// =========================================================================
#define ASTR 40                       // smem row stride in bf16 (32 + 8 pad)
#define STG_ROWS 384                  // 64(Ahi)+64(Alo)+128(Bhi)+128(Blo)
#define NSTAGE 2
#define GEMM_SMEM (NSTAGE * STG_ROWS * ASTR * 2)   // 61440 B

__global__ __launch_bounds__(256, 3)
void gemm_mma_kernel(const __nv_bfloat16* __restrict__ Ahi,
                     const __nv_bfloat16* __restrict__ Alo,
                     const __nv_bfloat16* __restrict__ A2hi,
                     const __nv_bfloat16* __restrict__ A2lo, int Ks,
                     const __nv_bfloat16* __restrict__ Whi,
                     const __nv_bfloat16* __restrict__ Wlo,
                     const float* __restrict__ bias,
                     const float* __restrict__ bias2, int bhalf,
                     const float* __restrict__ bn_g,
                     const float* __restrict__ bn_b,
                     float* __restrict__ Cf,
                     __nv_bfloat16* __restrict__ Chi,
                     __nv_bfloat16* __restrict__ Clo,
                     const float* __restrict__ w4,
                     float* __restrict__ outp,
                     int M, int Nc, int K, int mode)
{
    extern __shared__ __nv_bfloat16 smem[];

    const int tid = threadIdx.x;
    const int wid = tid >> 5;
    const int lane = tid & 31;
    const int warp_m = wid >> 2;
    const int warp_n = wid & 3;
    const int m0 = blockIdx.y * 64;
    const int n0 = blockIdx.x * 128;

    float acc[2][4][4] = {};
    const int NCH = K >> 5;

    const int ar = tid >> 2, aq = tid & 3;   // A: 64 rows x 4 16B pieces
    const int br = tid >> 2, bq = tid & 3;   // B: rows br, br+64

    auto issue = [&](int c) {
        int st = c & 1;
        uint32_t sb = smem_u32(smem + st * (STG_ROWS * ASTR));
        int k0 = c * 32;
        {
            int grow = m0 + ar;
            bool ap = grow < M;
            int gr = ap ? grow : (M - 1);
            const __nv_bfloat16 *shi, *slo;
            if (k0 < Ks) {
                shi = Ahi + (size_t)gr * Ks + k0;
                slo = Alo + (size_t)gr * Ks + k0;
            } else {
                shi = A2hi + (size_t)gr * (K - Ks) + (k0 - Ks);
                slo = A2lo + (size_t)gr * (K - Ks) + (k0 - Ks);
            }
            uint32_t ad = sb + (uint32_t)(ar * ASTR + aq * 8) * 2;
            cp16(ad,                  shi + aq * 8, ap);
            cp16(ad + 64 * ASTR * 2,  slo + aq * 8, ap);
        }
        #pragma unroll
        for (int h = 0; h < 2; h++) {
            int gn = n0 + br + h * 64;
            bool bp = gn < Nc;
            int gc = bp ? gn : (Nc - 1);
            uint32_t bd = sb + (uint32_t)((128 + br + h * 64) * ASTR + bq * 8) * 2;
            cp16(bd,                   Whi + (size_t)gc * K + k0 + bq * 8, bp);
            cp16(bd + 128 * ASTR * 2,  Wlo + (size_t)gc * K + k0 + bq * 8, bp);
        }
        cp_commit();
    };

    issue(0);

    for (int c = 0; c < NCH; c++) {
        cp_wait0();
        __syncthreads();
        if (c + 1 < NCH) issue(c + 1);

        __nv_bfloat16* base = smem + (c & 1) * (STG_ROWS * ASTR);
        __nv_bfloat16* sAhi = base;
        __nv_bfloat16* sAlo = base + 64 * ASTR;
        __nv_bfloat16* sBhi = base + 128 * ASTR;
        __nv_bfloat16* sBlo = base + 256 * ASTR;

        #pragma unroll
        for (int ks = 0; ks < 2; ks++) {
            const int kb = ks * 16;
            uint32_t ahi[2][4], alo[2][4];
            #pragma unroll
            for (int mi = 0; mi < 2; mi++) {
                int row = warp_m * 32 + mi * 16 + (lane & 15);
                int col = kb + ((lane >> 4) << 3);
                ldsm4(ahi[mi], smem_u32(&sAhi[row * ASTR + col]));
                ldsm4(alo[mi], smem_u32(&sAlo[row * ASTR + col]));
            }
            uint32_t bhi[4][2], blo[4][2];
            #pragma unroll
            for (int pj = 0; pj < 2; pj++) {
                int row = warp_n * 32 + pj * 16 + ((lane & 16) >> 1) + (lane & 7);
                int col = kb + (lane & 8);
                uint32_t r4[4];
                ldsm4(r4, smem_u32(&sBhi[row * ASTR + col]));
                bhi[pj * 2][0] = r4[0]; bhi[pj * 2][1] = r4[1];
                bhi[pj * 2 + 1][0] = r4[2]; bhi[pj * 2 + 1][1] = r4[3];
                ldsm4(r4, smem_u32(&sBlo[row * ASTR + col]));
                blo[pj * 2][0] = r4[0]; blo[pj * 2][1] = r4[1];
                blo[pj * 2 + 1][0] = r4[2]; blo[pj * 2 + 1][1] = r4[3];
            }
            #pragma unroll
            for (int mi = 0; mi < 2; mi++)
                #pragma unroll
                for (int nj = 0; nj < 4; nj++)
                    mma16816(acc[mi][nj], ahi[mi], bhi[nj]);
            #pragma unroll
            for (int mi = 0; mi < 2; mi++)
                #pragma unroll
                for (int nj = 0; nj < 4; nj++)
                    mma16816(acc[mi][nj], alo[mi], bhi[nj]);
            #pragma unroll
            for (int mi = 0; mi < 2; mi++)
                #pragma unroll
                for (int nj = 0; nj < 4; nj++)
                    mma16816(acc[mi][nj], ahi[mi], blo[nj]);
        }
        __syncthreads();
    }

    // ---- mode 3: fused lrelu + dot(w4) + atomicAdd into outp --------------
    if (mode == 3) {
        float pA[2] = {0.f, 0.f}, pB[2] = {0.f, 0.f};
        #pragma unroll
        for (int mi = 0; mi < 2; mi++) {
            #pragma unroll
            for (int nj = 0; nj < 4; nj++) {
                int cb = n0 + warp_n * 32 + nj * 8 + 2 * (lane & 3);
                if (cb + 1 >= Nc + 1) continue;   // cb >= Nc
                if (cb >= Nc) continue;
                float b0 = (cb < bhalf) ? bias[cb] : bias2[cb - bhalf];
                float b1 = (cb + 1 < bhalf) ? bias[cb + 1] : bias2[cb + 1 - bhalf];
                float w0 = w4[cb], w1 = w4[cb + 1];
                float v;
                v = acc[mi][nj][0] + b0; v = v > 0.f ? v : 0.1f * v; pA[mi] += v * w0;
                v = acc[mi][nj][1] + b1; v = v > 0.f ? v : 0.1f * v; pA[mi] += v * w1;
                v = acc[mi][nj][2] + b0; v = v > 0.f ? v : 0.1f * v; pB[mi] += v * w0;
                v = acc[mi][nj][3] + b1; v = v > 0.f ? v : 0.1f * v; pB[mi] += v * w1;
            }
        }
        // reduce across the 4 lanes (lane&3) sharing each row
        #pragma unroll
        for (int o = 1; o < 4; o <<= 1) {
            pA[0] += __shfl_xor_sync(0xffffffffu, pA[0], o);
            pA[1] += __shfl_xor_sync(0xffffffffu, pA[1], o);
            pB[0] += __shfl_xor_sync(0xffffffffu, pB[0], o);
            pB[1] += __shfl_xor_sync(0xffffffffu, pB[1], o);
        }
        if ((lane & 3) == 0 && n0 + warp_n * 32 < Nc) {
            #pragma unroll
            for (int mi = 0; mi < 2; mi++) {
                int rA = m0 + warp_m * 32 + mi * 16 + (lane >> 2);
                int rB = rA + 8;
                if (rA < M) atomicAdd(&outp[rA], pA[mi]);
                if (rB < M) atomicAdd(&outp[rB], pB[mi]);
            }
        }
        return;
    }

    // epilogue (modes 0/1/2)
    const float inv_bn = rsqrtf(1.f + 1e-5f);
    float sc[4][2], sh[4][2];
    #pragma unroll
    for (int nj = 0; nj < 4; nj++) {
        int cb = n0 + warp_n * 32 + nj * 8 + 2 * (lane & 3);
        #pragma unroll
        for (int h = 0; h < 2; h++) {
            int col = cb + h;
            int cg = (col < Nc) ? col : 0;
            float b = (cg < bhalf) ? bias[cg] : bias2[cg - bhalf];
            if (mode == 1) {
                float s = bn_g[cg] * inv_bn;
                sc[nj][h] = s; sh[nj][h] = b * s + bn_b[cg];
            } else {
                sc[nj][h] = 1.f; sh[nj][h] = b;
            }
        }
    }
    const bool act = (mode != 0);
    #pragma unroll
    for (int mi = 0; mi < 2; mi++) {
        int rA = m0 + warp_m * 32 + mi * 16 + (lane >> 2);
        int rB = rA + 8;
        #pragma unroll
        for (int nj = 0; nj < 4; nj++) {
            int cb = n0 + warp_n * 32 + nj * 8 + 2 * (lane & 3);
            if (cb >= Nc) continue;
            float2 v0, v1;
            v0.x = acc[mi][nj][0] * sc[nj][0] + sh[nj][0];
            v0.y = acc[mi][nj][1] * sc[nj][1] + sh[nj][1];
            v1.x = acc[mi][nj][2] * sc[nj][0] + sh[nj][0];
            v1.y = acc[mi][nj][3] * sc[nj][1] + sh[nj][1];
            if (act) {
                v0.x = v0.x > 0.f ? v0.x : 0.1f * v0.x;
                v0.y = v0.y > 0.f ? v0.y : 0.1f * v0.y;
                v1.x = v1.x > 0.f ? v1.x : 0.1f * v1.x;
                v1.y = v1.y > 0.f ? v1.y : 0.1f * v1.y;
            }
            if (Cf) {
                if (rA < M) *reinterpret_cast<float2*>(&Cf[(size_t)rA * Nc + cb]) = v0;
                if (rB < M) *reinterpret_cast<float2*>(&Cf[(size_t)rB * Nc + cb]) = v1;
            }
            if (Chi) {
                __nv_bfloat16 h0 = __float2bfloat16_rn(v0.x);
                __nv_bfloat16 h1 = __float2bfloat16_rn(v0.y);
                __nv_bfloat16 h2 = __float2bfloat16_rn(v1.x);
                __nv_bfloat16 h3 = __float2bfloat16_rn(v1.y);
                __nv_bfloat162 phA = __halves2bfloat162(h0, h1);
                __nv_bfloat162 phB = __halves2bfloat162(h2, h3);
                __nv_bfloat162 plA = __halves2bfloat162(
                    __float2bfloat16_rn(v0.x - __bfloat162float(h0)),
                    __float2bfloat16_rn(v0.y - __bfloat162float(h1)));
                __nv_bfloat162 plB = __halves2bfloat162(
                    __float2bfloat16_rn(v1.x - __bfloat162float(h2)),
                    __float2bfloat16_rn(v1.y - __bfloat162float(h3)));
                if (rA < M) {
                    *reinterpret_cast<__nv_bfloat162*>(&Chi[(size_t)rA * Nc + cb]) = phA;
                    *reinterpret_cast<__nv_bfloat162*>(&Clo[(size_t)rA * Nc + cb]) = plA;
                }
                if (rB < M) {
                    *reinterpret_cast<__nv_bfloat162*>(&Chi[(size_t)rB * Nc + cb]) = phB;
                    *reinterpret_cast<__nv_bfloat162*>(&Clo[(size_t)rB * Nc + cb]) = plB;
                }
            }
        }
    }
}

// ---------------- activation split prep + out init -------------------------
__global__ void aprep_kernel(const float* __restrict__ A,
                             __nv_bfloat16* __restrict__ hi,
                             __nv_bfloat16* __restrict__ lo, int n,
                             float* __restrict__ outp,
                             const float* __restrict__ b4, int N)
{
    int i = blockIdx.x * blockDim.x + threadIdx.x;
    if (i < N) outp[i] = b4[0];     // init d_out for fused head atomics
    if (i >= n) return;
    float v = A[i];
    __nv_bfloat16 h = __float2bfloat16_rn(v);
    hi[i] = h;
    lo[i] = __float2bfloat16_rn(v - __bfloat162float(h));
}

// ---------------- fused weight prep (all 14 matrices, one launch) ---------
struct WPEntry { const float* W; int K; int lgNc; int off; int start; };
struct WPArgs  { WPEntry e[14]; int total; };

__global__ void wprep_all_kernel(WPArgs args,
                                 __nv_bfloat16* __restrict__ Wt_hi,
                                 __nv_bfloat16* __restrict__ Wt_lo)
{
    int gid = blockIdx.x * blockDim.x + threadIdx.x;
    if (gid >= args.total) return;
    int r = 0;
    #pragma unroll
    for (int i = 1; i < 14; i++)
        if (gid >= args.e[i].start) r = i;
    const WPEntry& en = args.e[r];
    int e = gid - en.start;
    int k = e >> en.lgNc;
    int n = e & ((1 << en.lgNc) - 1);
    float v = en.W[e];
    __nv_bfloat16 hi = __float2bfloat16_rn(v);
    size_t dst = (size_t)en.off + (size_t)n * en.K + k;
    Wt_hi[dst] = hi;
    Wt_lo[dst] = __float2bfloat16_rn(v - __bfloat162float(hi));
}

// ---------------- CSR build ------------------------------------------------
__global__ void hist_kernel(const int* __restrict__ ei, int* __restrict__ cnt,
                            int E, int N)
{
    int i = blockIdx.x * blockDim.x + threadIdx.x;
    int Et = E + N;
    if (i >= Et) return;
    int d = (i < E) ? ei[E + i] : (i - E);
    atomicAdd(&cnt[d], 1);
}

__global__ __launch_bounds__(1024)
void scan_kernel(const int* __restrict__ cnt, int* __restrict__ rowptr,
                 int* __restrict__ cursor, int N)
{
    __shared__ int part[1024];
    const int t = threadIdx.x;
    const int CH = (N + 1023) / 1024;
    int base = t * CH;
    int s = 0;
    for (int i = 0; i < CH; i++)
        if (base + i < N) s += cnt[base + i];
    part[t] = s;
    __syncthreads();
    for (int d = 1; d < 1024; d <<= 1) {
        int v = (t >= d) ? part[t - d] : 0;
        __syncthreads();
        part[t] += v;
        __syncthreads();
    }
    int run = part[t] - s;
    for (int i = 0; i < CH; i++) {
        int idx = base + i;
        if (idx < N) {
            rowptr[idx] = run;
            cursor[idx] = run;
            run += cnt[idx];
        }
    }
    if (t == 0) rowptr[N] = part[1023];
}

__global__ void fill_kernel(const int* __restrict__ ei, int* __restrict__ cursor,
                            int* __restrict__ csr_src, int E, int N)
{
    int i = blockIdx.x * blockDim.x + threadIdx.x;
    int Et = E + N;
    if (i >= Et) return;
    int s, d;
    if (i < E) { s = ei[i]; d = ei[E + i]; }
    else       { s = d = i - E; }
    int p = atomicAdd(&cursor[d], 1);
    csr_src[p] = s;
}

// =========================================================================
// Fused GAT layer (champion version): warp per dst node, online softmax,
// depth-1 prefetch; bias + LayerNorm + LeakyReLU(0.1) + residual; writes g
// (fp32) and its bf16 hi/lo split.
// xlr layout [N][512]: xl cols 0-255, xr cols 256-511.
// =========================================================================
__global__ __launch_bounds__(256)
void gat_fused_kernel(const float* __restrict__ xlr,
                      const int* __restrict__ csr_src,
                      const int* __restrict__ rowptr,
                      const float* __restrict__ att,
                      const float* __restrict__ gbias,
                      const float* __restrict__ lng,
                      const float* __restrict__ lnb,
                      const float* __restrict__ gres,
                      float* __restrict__ g,
                      __nv_bfloat16* __restrict__ ghi,
                      __nv_bfloat16* __restrict__ glo, int N)
{
    int warp = (blockIdx.x * blockDim.x + threadIdx.x) >> 5;
    int lane = threadIdx.x & 31;
    if (warp >= N) return;
    const int cb = lane * 8;

    float4 xr0 = *reinterpret_cast<const float4*>(xlr + (size_t)warp * 512 + 256 + cb);
    float4 xr1 = *reinterpret_cast<const float4*>(xlr + (size_t)warp * 512 + 256 + cb + 4);
    float4 at0 = *reinterpret_cast<const float4*>(att + cb);
    float4 at1 = *reinterpret_cast<const float4*>(att + cb + 4);

    int beg = rowptr[warp], end = rowptr[warp + 1];

    float m = -1e30f, s = 0.f;
    float acc[8] = {};

    float4 a0, a1;
    {
        int sidx = csr_src[beg];
        a0 = *reinterpret_cast<const float4*>(xlr + (size_t)sidx * 512 + cb);
        a1 = *reinterpret_cast<const float4*>(xlr + (size_t)sidx * 512 + cb + 4);
    }

    for (int j = beg; j < end; j++) {
        float4 c0 = a0, c1 = a1;
        if (j + 1 < end) {
            int sidx = csr_src[j + 1];
            a0 = *reinterpret_cast<const float4*>(xlr + (size_t)sidx * 512 + cb);
            a1 = *reinterpret_cast<const float4*>(xlr + (size_t)sidx * 512 + cb + 4);
        }
        float t, p = 0.f;
        t = c0.x + xr0.x; t = t > 0.f ? t : 0.2f * t; p += t * at0.x;
        t = c0.y + xr0.y; t = t > 0.f ? t : 0.2f * t; p += t * at0.y;
        t = c0.z + xr0.z; t = t > 0.f ? t : 0.2f * t; p += t * at0.z;
        t = c0.w + xr0.w; t = t > 0.f ? t : 0.2f * t; p += t * at0.w;
        t = c1.x + xr1.x; t = t > 0.f ? t : 0.2f * t; p += t * at1.x;
        t = c1.y + xr1.y; t = t > 0.f ? t : 0.2f * t; p += t * at1.y;
        t = c1.z + xr1.z; t = t > 0.f ? t : 0.2f * t; p += t * at1.z;
        t = c1.w + xr1.w; t = t > 0.f ? t : 0.2f * t; p += t * at1.w;
        p += __shfl_xor_sync(0xffffffffu, p, 1);
        p += __shfl_xor_sync(0xffffffffu, p, 2);
        float mn = fmaxf(m, p);
        float cf = __expf(m - mn);
        float w  = __expf(p - mn);
        m = mn;
        s = s * cf + w;
        acc[0] = acc[0] * cf + w * c0.x;
        acc[1] = acc[1] * cf + w * c0.y;
        acc[2] = acc[2] * cf + w * c0.z;
        acc[3] = acc[3] * cf + w * c0.w;
        acc[4] = acc[4] * cf + w * c1.x;
        acc[5] = acc[5] * cf + w * c1.y;
        acc[6] = acc[6] * cf + w * c1.z;
        acc[7] = acc[7] * cf + w * c1.w;
    }

    float inv_s = 1.f / (s + 1e-16f);
    float out[8];
    {
        float4 b0 = *reinterpret_cast<const float4*>(gbias + cb);
        float4 b1 = *reinterpret_cast<const float4*>(gbias + cb + 4);
        out[0] = acc[0] * inv_s + b0.x;
        out[1] = acc[1] * inv_s + b0.y;
        out[2] = acc[2] * inv_s + b0.z;
        out[3] = acc[3] * inv_s + b0.w;
        out[4] = acc[4] * inv_s + b1.x;
        out[5] = acc[5] * inv_s + b1.y;
        out[6] = acc[6] * inv_s + b1.z;
        out[7] = acc[7] * inv_s + b1.w;
    }
    float sum = 0.f;
    #pragma unroll
    for (int i = 0; i < 8; i++) sum += out[i];
    #pragma unroll
    for (int o = 16; o; o >>= 1) sum += __shfl_xor_sync(0xffffffffu, sum, o);
    float mu = sum * (1.f / 256.f);
    float var = 0.f;
    #pragma unroll
    for (int i = 0; i < 8; i++) { float dd = out[i] - mu; var += dd * dd; }
    #pragma unroll
    for (int o = 16; o; o >>= 1) var += __shfl_xor_sync(0xffffffffu, var, o);
    var *= (1.f / 256.f);
    float inv = rsqrtf(var + 1e-5f);

    float4 lg0 = *reinterpret_cast<const float4*>(lng + cb);
    float4 lg1 = *reinterpret_cast<const float4*>(lng + cb + 4);
    float4 lb0 = *reinterpret_cast<const float4*>(lnb + cb);
    float4 lb1 = *reinterpret_cast<const float4*>(lnb + cb + 4);
    const float* rrow = gres + (size_t)warp * HID + cb;
    float4 g0 = *reinterpret_cast<const float4*>(rrow);
    float4 g1 = *reinterpret_cast<const float4*>(rrow + 4);

    float lgv[8] = {lg0.x, lg0.y, lg0.z, lg0.w, lg1.x, lg1.y, lg1.z, lg1.w};
    float lbv[8] = {lb0.x, lb0.y, lb0.z, lb0.w, lb1.x, lb1.y, lb1.z, lb1.w};
    float gv[8]  = {g0.x, g0.y, g0.z, g0.w, g1.x, g1.y, g1.z, g1.w};
    #pragma unroll
    for (int i = 0; i < 8; i++) {
        float o_ = (out[i] - mu) * inv * lgv[i] + lbv[i];
        o_ = o_ > 0.f ? o_ : 0.1f * o_;
        gv[i] += o_;
    }
    float* grow = g + (size_t)warp * HID + cb;
    *reinterpret_cast<float4*>(grow)     = make_float4(gv[0], gv[1], gv[2], gv[3]);
    *reinterpret_cast<float4*>(grow + 4) = make_float4(gv[4], gv[5], gv[6], gv[7]);

    union { __nv_bfloat162 b[4]; uint4 u; } ph, pl;
    #pragma unroll
    for (int i = 0; i < 4; i++) {
        __nv_bfloat16 h0 = __float2bfloat16_rn(gv[2 * i]);
        __nv_bfloat16 h1 = __float2bfloat16_rn(gv[2 * i + 1]);
        ph.b[i] = __halves2bfloat162(h0, h1);
        pl.b[i] = __halves2bfloat162(
            __float2bfloat16_rn(gv[2 * i]     - __bfloat162float(h0)),
            __float2bfloat16_rn(gv[2 * i + 1] - __bfloat162float(h1)));
    }
    *reinterpret_cast<uint4*>(ghi + (size_t)warp * HID + cb) = ph.u;
    *reinterpret_cast<uint4*>(glo + (size_t)warp * HID + cb) = pl.u;
}

// =========================================================================
extern "C" void kernel_launch(void* const* d_in, const int* in_sizes, int n_in,
                              void* d_out, int out_size)
{
    const float* x       = (const float*)d_in[0];
    const int*   ei      = (const int*)  d_in[1];
    const float* mlp_w1  = (const float*)d_in[2];
    const float* mlp_b1  = (const float*)d_in[3];
    const float* bn1_g   = (const float*)d_in[4];
    const float* bn1_b   = (const float*)d_in[5];
    const float* mlp_w2  = (const float*)d_in[6];
    const float* mlp_b2  = (const float*)d_in[7];
    const float* bn2_g   = (const float*)d_in[8];
    const float* bn2_b   = (const float*)d_in[9];
    const float* mlp_w3  = (const float*)d_in[10];
    const float* mlp_b3  = (const float*)d_in[11];
    const float* gat_wl  = (const float*)d_in[12];
    const float* gat_bl  = (const float*)d_in[13];
    const float* gat_wr  = (const float*)d_in[14];
    const float* gat_br  = (const float*)d_in[15];
    const float* gat_att = (const float*)d_in[16];
    const float* gat_bias= (const float*)d_in[17];
    const float* ln_g    = (const float*)d_in[18];
    const float* ln_b    = (const float*)d_in[19];
    const float* head_w1 = (const float*)d_in[20];
    const float* head_b1 = (const float*)d_in[21];
    const float* hbn1_g  = (const float*)d_in[22];
    const float* hbn1_b  = (const float*)d_in[23];
    const float* head_w2 = (const float*)d_in[24];
    const float* head_b2 = (const float*)d_in[25];
    const float* hbn2_g  = (const float*)d_in[26];
    const float* hbn2_b  = (const float*)d_in[27];
    const float* head_w3 = (const float*)d_in[28];
    const float* head_b3 = (const float*)d_in[29];
    const float* head_w4 = (const float*)d_in[30];
    const float* head_b4 = (const float*)d_in[31];

    int N = in_sizes[0] / 128;
    int E = in_sizes[1] / 2;
    if (N > NMAX) N = NMAX;
    if (E > EMAX) E = EMAX;
    int Et = E + N;

    float *xmlp, *g, *xlr;
    int *cnt, *cursor, *rowptr, *csr_src;
    __nv_bfloat16 *whi, *wlo, *xhi, *xlo, *h1hi, *h1lo, *h2hi, *h2lo;
    __nv_bfloat16 *xmhi, *xmlo, *ghi, *glo, *t1hi, *t1lo, *t2hi, *t2lo;
    cudaGetSymbolAddress((void**)&xmlp,    g_xmlp);
    cudaGetSymbolAddress((void**)&g,       g_g);
    cudaGetSymbolAddress((void**)&xlr,     g_xlr);
    cudaGetSymbolAddress((void**)&cnt,     g_cnt);
    cudaGetSymbolAddress((void**)&cursor,  g_cursor);
    cudaGetSymbolAddress((void**)&rowptr,  g_rowptr);
    cudaGetSymbolAddress((void**)&csr_src, g_csr_src);
    cudaGetSymbolAddress((void**)&whi,     g_wthi);
    cudaGetSymbolAddress((void**)&wlo,     g_wtlo);
    cudaGetSymbolAddress((void**)&xhi,     g_xhi);
    cudaGetSymbolAddress((void**)&xlo,     g_xlo);
    cudaGetSymbolAddress((void**)&h1hi,    g_h1hi);
    cudaGetSymbolAddress((void**)&h1lo,    g_h1lo);
    cudaGetSymbolAddress((void**)&h2hi,    g_h2hi);
    cudaGetSymbolAddress((void**)&h2lo,    g_h2lo);
    cudaGetSymbolAddress((void**)&xmhi,    g_xmhi);
    cudaGetSymbolAddress((void**)&xmlo,    g_xmlo);
    cudaGetSymbolAddress((void**)&ghi,     g_ghi);
    cudaGetSymbolAddress((void**)&glo,     g_glo);
    cudaGetSymbolAddress((void**)&t1hi,    g_t1hi);
    cudaGetSymbolAddress((void**)&t1lo,    g_t1lo);
    cudaGetSymbolAddress((void**)&t2hi,    g_t2hi);
    cudaGetSymbolAddress((void**)&t2lo,    g_t2lo);

    cudaFuncSetAttribute(gemm_mma_kernel,
                         cudaFuncAttributeMaxDynamicSharedMemorySize, GEMM_SMEM);

    dim3 blk(256);
    const int OFF_M1 = 0;
    const int OFF_M2 = 32768;
    const int OFF_M3 = 98304;
    const int OFF_GAT = 163840;
    const int OFF_H1 = 688128;
    const int OFF_H2 = 819200;
    const int OFF_H3 = 851968;

    WPArgs wa;
    int cur = 0, idx = 0;
    auto addw = [&](const float* W, int K, int lg, int off) {
        wa.e[idx].W = W; wa.e[idx].K = K; wa.e[idx].lgNc = lg;
        wa.e[idx].off = off; wa.e[idx].start = cur;
        cur += K << lg; idx++;
    };
    addw(mlp_w1, 128, 8, OFF_M1);
    addw(mlp_w2, 256, 8, OFF_M2);
    addw(mlp_w3, 256, 8, OFF_M3);
    for (int l = 0; l < 4; l++) {
        addw(gat_wl + (size_t)l * 65536, 256, 8, OFF_GAT + l * 131072);
        addw(gat_wr + (size_t)l * 65536, 256, 8, OFF_GAT + l * 131072 + 65536);
    }
    addw(head_w1, 512, 8, OFF_H1);
    addw(head_w2, 256, 7, OFF_H2);
    addw(head_w3, 128, 6, OFF_H3);
    wa.total = cur;
    wprep_all_kernel<<<(cur + 255) / 256, blk>>>(wa, whi, wlo);
    aprep_kernel<<<(N * 128 + 255) / 256, blk>>>(x, xhi, xlo, N * 128,
                                                 (float*)d_out, head_b4, N);

    const int BIG = 1 << 30;
    auto mm = [&](const __nv_bfloat16* Ahi, const __nv_bfloat16* Alo,
                  const __nv_bfloat16* A2hi, const __nv_bfloat16* A2lo, int Ks,
                  int off, const float* bias, const float* bias2, int bhalf,
                  const float* bg, const float* bb,
                  float* Cf, __nv_bfloat16* Chi, __nv_bfloat16* Clo,
                  const float* w4, float* outp,
                  int Nc, int K, int mode) {
        dim3 grid((unsigned)((Nc + 127) / 128), (unsigned)((N + 63) / 64));
        gemm_mma_kernel<<<grid, blk, GEMM_SMEM>>>(Ahi, Alo,
            A2hi ? A2hi : Ahi, A2lo ? A2lo : Alo, Ks,
            whi + off, wlo + off, bias, bias2 ? bias2 : bias, bhalf,
            bg, bb, Cf, Chi, Clo, w4, outp, N, Nc, K, mode);
    };

    // Feature MLP
    mm(xhi, xlo, nullptr, nullptr, 128, OFF_M1, mlp_b1, nullptr, BIG,
       bn1_g, bn1_b, nullptr, h1hi, h1lo, nullptr, nullptr, 256, 128, 1);
    mm(h1hi, h1lo, nullptr, nullptr, 256, OFF_M2, mlp_b2, nullptr, BIG,
       bn2_g, bn2_b, nullptr, h2hi, h2lo, nullptr, nullptr, 256, 256, 1);
    mm(h2hi, h2lo, nullptr, nullptr, 256, OFF_M3, mlp_b3, nullptr, BIG,
       nullptr, nullptr, xmlp, xmhi, xmlo, nullptr, nullptr, 256, 256, 0);

    // layer 0 merged xl|xr GEMM
    mm(xmhi, xmlo, nullptr, nullptr, 256, OFF_GAT, gat_bl, gat_br, 256,
       nullptr, nullptr, xlr, nullptr, nullptr, nullptr, nullptr, 512, 256, 0);

    // ---- CSR build --------------------------------------------------------
    cudaMemsetAsync(cnt, 0, (size_t)N * sizeof(int));
    hist_kernel<<<(Et + 255) / 256, blk>>>(ei, cnt, E, N);
    scan_kernel<<<1, 1024>>>(cnt, rowptr, cursor, N);
    fill_kernel<<<(Et + 255) / 256, blk>>>(ei, cursor, csr_src, E, N);

    const int gat_grid = (N * 32 + 255) / 256;
    for (int l = 0; l < 4; l++) {
        const float* at  = gat_att + (size_t)l * 256;
        const float* gb  = gat_bias+ (size_t)l * 256;
        const float* lg  = ln_g    + (size_t)l * 256;
        const float* lb  = ln_b    + (size_t)l * 256;

        if (l > 0) {
            mm(ghi, glo, nullptr, nullptr, 256, OFF_GAT + l * 131072,
               gat_bl + (size_t)l * 256, gat_br + (size_t)l * 256, 256,
               nullptr, nullptr, xlr, nullptr, nullptr, nullptr, nullptr, 512, 256, 0);
        }
        gat_fused_kernel<<<gat_grid, blk>>>(xlr, csr_src, rowptr, at, gb, lg, lb,
                                            (l == 0) ? xmlp : g, g, ghi, glo, N);
    }

    // head (concat fused via A|A2 split; final dot fused into last GEMM)
    mm(xmhi, xmlo, ghi, glo, 256, OFF_H1, head_b1, nullptr, BIG,
       hbn1_g, hbn1_b, nullptr, t1hi, t1lo, nullptr, nullptr, 256, 512, 1);
    mm(t1hi, t1lo, nullptr, nullptr, 256, OFF_H2, head_b2, nullptr, BIG,
       hbn2_g, hbn2_b, nullptr, t2hi, t2lo, nullptr, nullptr, 128, 256, 1);
    mm(t2hi, t2lo, nullptr, nullptr, 128, OFF_H3, head_b3, nullptr, BIG,
       nullptr, nullptr, nullptr, nullptr, nullptr, head_w4, (float*)d_out,
       64, 128, 3);
}